// round 1
// baseline (speedup 1.0000x reference)
#include <cuda_runtime.h>
#include <math.h>

// ---------------- problem constants ----------------
#define NB   64      // batch
#define LL   2048    // raw length
#define MS   12      // sensors
#define DD   128     // embed dim
#define PP   16      // emb kernel
#define SSTR 8       // emb stride
#define TT   256     // tokens after emb
#define KC   5       // dw kernel
#define DR   32      // SE reduced
#define NLB  3
#define NMB  2
#define DI   256     // mamba inner
#define DCV  4       // mamba conv kernel
#define DSN  16      // SSM state
#define RKD  8       // dt rank
#define CC   18      // classes
#define BMR  768     // NB*MS
#define BT   16384   // NB*TT

// ---------------- scratch (device globals, no allocs) ----------------
__device__ float g_xe [BMR*DD*TT];   // u  [bm][d][t]
__device__ float g_v  [BMR*DD*TT];   // v
__device__ float g_w  [BMR*DD*TT];   // w
__device__ float g_s  [BMR*DD];
__device__ float g_a  [BMR*DD];
__device__ float g_x2 [BT*DD];       // [b*T+t][d]
__device__ float g_xz [BT*2*DI];     // [bt][e]
__device__ float g_xc [BT*DI];       // [bt][c]
__device__ float g_dbl[BT*40];       // [bt][k]
__device__ float g_dt [BT*DI];
__device__ float g_y  [BT*DI];
__device__ float g_out[BT*DD];

// ---------------- stage 1: embedding conv ----------------
__global__ void k_emb(const float* __restrict__ xin,
                      const float* __restrict__ w,
                      const float* __restrict__ bias) {
    __shared__ float srow[LL];
    __shared__ float sw[DD*PP];
    __shared__ float sb[DD];
    int bm = blockIdx.x;
    int b = bm / MS, m = bm % MS;
    const float* xp = xin + (size_t)b * (LL*MS) + m;
    for (int l = threadIdx.x; l < LL; l += blockDim.x) srow[l] = xp[(size_t)l * MS];
    for (int i = threadIdx.x; i < DD*PP; i += blockDim.x) sw[i] = w[i];
    for (int i = threadIdx.x; i < DD; i += blockDim.x) sb[i] = bias[i];
    __syncthreads();
    int t = threadIdx.x;            // 0..255
    int base = t * SSTR - 4;        // pad 4 left
    float* outp = g_xe + (size_t)bm * (DD*TT);
    for (int d = 0; d < DD; d++) {
        float acc = sb[d];
        #pragma unroll
        for (int p = 0; p < PP; p++) {
            int l = base + p;
            if (l >= 0 && l < LL) acc += sw[d*PP + p] * srow[l];
        }
        outp[d*TT + t] = acc;
    }
}

// ---------------- block: depthwise conv + exact gelu ----------------
__global__ void k_dwgelu(const float* __restrict__ dww, const float* __restrict__ dwb) {
    int idx = blockIdx.x * blockDim.x + threadIdx.x;
    if (idx >= BMR*DD*TT) return;
    int t = idx & (TT-1);
    int d = (idx >> 8) & (DD-1);
    float acc = dwb[d];
    #pragma unroll
    for (int k = 0; k < KC; k++) {
        int tt = t + k - 2;
        if (tt >= 0 && tt < TT) acc += dww[d*KC + k] * g_xe[idx + (k-2)];
    }
    g_v[idx] = 0.5f * acc * (1.0f + erff(acc * 0.7071067811865475f));
}

// ---------------- block: pointwise GEMM (+bias), batched ----------------
// C[z](128e x 128t-tile) = A(128x128) @ B[z](128d x 256t) + bias
__global__ void __launch_bounds__(256) k_pw_gemm(const float* __restrict__ A,
                                                 const float* __restrict__ bias) {
    __shared__ __align__(16) float As[16][128];
    __shared__ __align__(16) float Bs[16][128];
    int z  = blockIdx.z;
    int bn = blockIdx.x * 128;
    const float* Bp = g_v + (size_t)z * (DD*TT);
    float*       Cp = g_w + (size_t)z * (DD*TT);
    int tid = threadIdx.x;
    int lr  = tid >> 2;           // 0..63
    int lk  = (tid & 3) << 2;     // 0,4,8,12
    int bkr = tid >> 5;           // 0..7
    int bnv = (tid & 31) << 2;    // 0..124
    int tr  = tid >> 4, tc = tid & 15;
    float acc[8][8];
    #pragma unroll
    for (int i = 0; i < 8; i++)
        #pragma unroll
        for (int j = 0; j < 8; j++) acc[i][j] = 0.0f;
    for (int kk = 0; kk < DD; kk += 16) {
        float4 a0 = *(const float4*)&A[(lr)*DD + kk + lk];
        float4 a1 = *(const float4*)&A[(64+lr)*DD + kk + lk];
        float4 b0 = *(const float4*)&Bp[(kk+bkr)*TT + bn + bnv];
        float4 b1 = *(const float4*)&Bp[(kk+bkr+8)*TT + bn + bnv];
        __syncthreads();
        As[lk+0][lr] = a0.x; As[lk+1][lr] = a0.y; As[lk+2][lr] = a0.z; As[lk+3][lr] = a0.w;
        As[lk+0][64+lr] = a1.x; As[lk+1][64+lr] = a1.y; As[lk+2][64+lr] = a1.z; As[lk+3][64+lr] = a1.w;
        *(float4*)&Bs[bkr  ][bnv] = b0;
        *(float4*)&Bs[bkr+8][bnv] = b1;
        __syncthreads();
        #pragma unroll
        for (int k = 0; k < 16; k++) {
            float ra[8], rb[8];
            *(float4*)&ra[0] = *(const float4*)&As[k][tr*4];
            *(float4*)&ra[4] = *(const float4*)&As[k][64 + tr*4];
            *(float4*)&rb[0] = *(const float4*)&Bs[k][tc*4];
            *(float4*)&rb[4] = *(const float4*)&Bs[k][64 + tc*4];
            #pragma unroll
            for (int i = 0; i < 8; i++)
                #pragma unroll
                for (int j = 0; j < 8; j++) acc[i][j] += ra[i]*rb[j];
        }
    }
    #pragma unroll
    for (int i = 0; i < 8; i++) {
        int r = (i < 4) ? (tr*4 + i) : (64 + tr*4 + i - 4);
        float bv = bias[r];
        #pragma unroll
        for (int j = 0; j < 8; j++) {
            int cc = (j < 4) ? (tc*4 + j) : (64 + tc*4 + j - 4);
            Cp[r*TT + bn + cc] = acc[i][j] + bv;
        }
    }
}

// ---------------- block: mean over t ----------------
__global__ void k_mean() {
    int bm = blockIdx.x, e = threadIdx.x;
    const float4* wp = (const float4*)(g_w + (size_t)bm*DD*TT + e*TT);
    float s = 0.0f;
    #pragma unroll 8
    for (int i = 0; i < TT/4; i++) { float4 v = wp[i]; s += v.x + v.y + v.z + v.w; }
    g_s[bm*DD + e] = s * (1.0f/TT);
}

// ---------------- block: SE MLP ----------------
__global__ void k_se(const float* __restrict__ w1, const float* __restrict__ b1,
                     const float* __restrict__ w2, const float* __restrict__ b2) {
    __shared__ float ss[DD];
    __shared__ float hh[DR];
    int bm = blockIdx.x, tid = threadIdx.x;
    ss[tid] = g_s[bm*DD + tid];
    __syncthreads();
    if (tid < DR) {
        float acc = b1[tid];
        for (int d = 0; d < DD; d++) acc += w1[tid*DD + d] * ss[d];
        hh[tid] = fmaxf(acc, 0.0f);
    }
    __syncthreads();
    float acc = b2[tid];
    #pragma unroll
    for (int j = 0; j < DR; j++) acc += w2[tid*DR + j] * hh[j];
    g_a[bm*DD + tid] = 1.0f / (1.0f + __expf(-acc));
}

// ---------------- block: u += w * a ----------------
__global__ void k_apply() {
    int idx = blockIdx.x * blockDim.x + threadIdx.x;
    if (idx >= BMR*DD*TT) return;
    int bm = idx >> 15;            // /32768
    int e  = (idx >> 8) & (DD-1);
    g_xe[idx] += g_w[idx] * g_a[bm*DD + e];
}

// ---------------- sensor mean + reshape to [bt][d] ----------------
__global__ void k_smean() {
    int t = blockIdx.x, b = blockIdx.y, d = threadIdx.x;
    float s = 0.0f;
    #pragma unroll
    for (int m = 0; m < MS; m++)
        s += g_xe[(size_t)(b*MS + m)*DD*TT + d*TT + t];
    g_x2[(size_t)(b*TT + t)*DD + d] = s * (1.0f/MS);
}

// ---------------- generic NT SGEMM for mamba projections ----------------
// mode 0: xz(16384x512) = x2(16384x128) @ in_w(512x128)^T
// mode 1: out(16384x128) = y(16384x256) @ out_w(128x256)^T
__global__ void __launch_bounds__(256) k_gemm_nt(int mode, const float* __restrict__ Bw, int K) {
    __shared__ __align__(16) float As[16][128];
    __shared__ __align__(16) float Bs[16][128];
    const float* A; float* C; int lda, ldc;
    if (mode == 0) { A = g_x2; lda = DD;  C = g_xz;  ldc = 2*DI; }
    else           { A = g_y;  lda = DI;  C = g_out; ldc = DD;   }
    int bm0 = blockIdx.y * 128, bn0 = blockIdx.x * 128;
    int tid = threadIdx.x;
    int lr = tid >> 2, lk = (tid & 3) << 2;
    int tr = tid >> 4, tc = tid & 15;
    float acc[8][8];
    #pragma unroll
    for (int i = 0; i < 8; i++)
        #pragma unroll
        for (int j = 0; j < 8; j++) acc[i][j] = 0.0f;
    for (int kk = 0; kk < K; kk += 16) {
        float4 a0 = *(const float4*)&A [(size_t)(bm0+lr)*lda + kk + lk];
        float4 a1 = *(const float4*)&A [(size_t)(bm0+64+lr)*lda + kk + lk];
        float4 b0 = *(const float4*)&Bw[(size_t)(bn0+lr)*K + kk + lk];
        float4 b1 = *(const float4*)&Bw[(size_t)(bn0+64+lr)*K + kk + lk];
        __syncthreads();
        As[lk+0][lr] = a0.x; As[lk+1][lr] = a0.y; As[lk+2][lr] = a0.z; As[lk+3][lr] = a0.w;
        As[lk+0][64+lr] = a1.x; As[lk+1][64+lr] = a1.y; As[lk+2][64+lr] = a1.z; As[lk+3][64+lr] = a1.w;
        Bs[lk+0][lr] = b0.x; Bs[lk+1][lr] = b0.y; Bs[lk+2][lr] = b0.z; Bs[lk+3][lr] = b0.w;
        Bs[lk+0][64+lr] = b1.x; Bs[lk+1][64+lr] = b1.y; Bs[lk+2][64+lr] = b1.z; Bs[lk+3][64+lr] = b1.w;
        __syncthreads();
        #pragma unroll
        for (int k = 0; k < 16; k++) {
            float ra[8], rb[8];
            *(float4*)&ra[0] = *(const float4*)&As[k][tr*4];
            *(float4*)&ra[4] = *(const float4*)&As[k][64 + tr*4];
            *(float4*)&rb[0] = *(const float4*)&Bs[k][tc*4];
            *(float4*)&rb[4] = *(const float4*)&Bs[k][64 + tc*4];
            #pragma unroll
            for (int i = 0; i < 8; i++)
                #pragma unroll
                for (int j = 0; j < 8; j++) acc[i][j] += ra[i]*rb[j];
        }
    }
    #pragma unroll
    for (int i = 0; i < 8; i++) {
        int r = (i < 4) ? (tr*4 + i) : (64 + tr*4 + i - 4);
        #pragma unroll
        for (int j = 0; j < 8; j++) {
            int cc = (j < 4) ? (tc*4 + j) : (64 + tc*4 + j - 4);
            C[(size_t)(bm0 + r)*ldc + bn0 + cc] = acc[i][j];
        }
    }
}

// ---------------- mamba: causal depthwise conv + silu ----------------
__global__ void k_convsilu(const float* __restrict__ cw, const float* __restrict__ cb) {
    int idx = blockIdx.x * blockDim.x + threadIdx.x;
    if (idx >= BT*DI) return;
    int c = idx & (DI-1);
    int t = (idx >> 8) & (TT-1);
    int b = idx >> 16;
    float acc = cb[c];
    #pragma unroll
    for (int j = 0; j < DCV; j++) {
        int tt = t - 3 + j;
        if (tt >= 0) acc += cw[c*DCV + j] * g_xz[(size_t)(b*TT + tt)*(2*DI) + c];
    }
    g_xc[idx] = acc / (1.0f + __expf(-acc));
}

// ---------------- mamba: dbl = xc @ xproj^T ----------------
__global__ void k_dbl(const float* __restrict__ xp) {
    __shared__ float sx[32][DI+1];
    int t0 = blockIdx.x * 32;
    for (int i = threadIdx.x; i < 32*DI; i += blockDim.x) {
        int tt = i >> 8, c = i & (DI-1);
        sx[tt][c] = g_xc[(size_t)(t0 + tt)*DI + c];
    }
    __syncthreads();
    for (int o = threadIdx.x; o < 32*40; o += blockDim.x) {
        int tt = o & 31, k = o >> 5;
        const float* wrow = xp + k*DI;
        float acc = 0.0f;
        #pragma unroll 8
        for (int c = 0; c < DI; c++) acc += wrow[c] * sx[tt][c];
        g_dbl[(size_t)(t0 + tt)*40 + k] = acc;
    }
}

// ---------------- mamba: dt = softplus(dtr @ dt_w^T + b) ----------------
__global__ void k_dt(const float* __restrict__ dtw, const float* __restrict__ dtb) {
    int idx = blockIdx.x * blockDim.x + threadIdx.x;
    if (idx >= BT*DI) return;
    int c = idx & (DI-1);
    int bt = idx >> 8;
    float acc = dtb[c];
    #pragma unroll
    for (int r = 0; r < RKD; r++) acc += dtw[c*RKD + r] * g_dbl[(size_t)bt*40 + r];
    g_dt[idx] = (acc > 20.0f) ? acc : log1pf(__expf(acc));
}

// ---------------- mamba: selective scan + gate ----------------
__global__ void k_scan(const float* __restrict__ Alog, const float* __restrict__ Dp) {
    __shared__ float sBC[TT][32];   // [t][Bm(16) | Cm(16)]
    int b = blockIdx.y;
    int c = blockIdx.x * blockDim.x + threadIdx.x;
    for (int i = threadIdx.x; i < TT*32; i += blockDim.x) {
        int tt = i >> 5, j = i & 31;
        sBC[tt][j] = g_dbl[(size_t)(b*TT + tt)*40 + 8 + j];
    }
    __syncthreads();
    float Av[DSN];
    #pragma unroll
    for (int s = 0; s < DSN; s++) Av[s] = -__expf(Alog[c*DSN + s]);
    float A0 = Av[0];
    bool structured = true;
    #pragma unroll
    for (int s = 0; s < DSN; s++)
        if (fabsf(Av[s] - (float)(s+1)*A0) > 1e-4f * fabsf(Av[s])) structured = false;
    float h[DSN];
    #pragma unroll
    for (int s = 0; s < DSN; s++) h[s] = 0.0f;
    float dpc = Dp[c];
    for (int t = 0; t < TT; t++) {
        size_t bt = (size_t)(b*TT + t);
        float dtv = g_dt[bt*DI + c];
        float xcv = g_xc[bt*DI + c];
        float zv  = g_xz[bt*(2*DI) + DI + c];
        float dtxc = dtv * xcv;
        float y = 0.0f;
        if (structured) {
            float r = __expf(dtv * A0);
            float p = 1.0f;
            #pragma unroll
            for (int s = 0; s < DSN; s++) {
                p *= r;
                h[s] = p*h[s] + dtxc*sBC[t][s];
                y += h[s]*sBC[t][16+s];
            }
        } else {
            #pragma unroll
            for (int s = 0; s < DSN; s++) {
                float dA = __expf(dtv * Av[s]);
                h[s] = dA*h[s] + dtxc*sBC[t][s];
                y += h[s]*sBC[t][16+s];
            }
        }
        float yv = y + dpc*xcv;
        yv = yv * (zv / (1.0f + __expf(-zv)));
        g_y[bt*DI + c] = yv;
    }
}

// ---------------- residual + layernorm (in place on g_x2) ----------------
__global__ void k_ln(const float* __restrict__ g, const float* __restrict__ bta) {
    __shared__ float red[4];
    int bt = blockIdx.x, d = threadIdx.x;
    float v = g_x2[(size_t)bt*DD + d] + g_out[(size_t)bt*DD + d];
    float s = v;
    #pragma unroll
    for (int o = 16; o > 0; o >>= 1) s += __shfl_xor_sync(0xffffffffu, s, o);
    if ((d & 31) == 0) red[d >> 5] = s;
    __syncthreads();
    float mean = (red[0] + red[1] + red[2] + red[3]) * (1.0f/DD);
    float dv = v - mean;
    float q = dv * dv;
    #pragma unroll
    for (int o = 16; o > 0; o >>= 1) q += __shfl_xor_sync(0xffffffffu, q, o);
    __syncthreads();
    if ((d & 31) == 0) red[d >> 5] = q;
    __syncthreads();
    float var = (red[0] + red[1] + red[2] + red[3]) * (1.0f/DD);
    g_x2[(size_t)bt*DD + d] = dv * rsqrtf(var + 1e-5f) * g[d] + bta[d];
}

// ---------------- xflat: [b][d][t] transpose into d_out ----------------
__global__ void k_xflat(float* __restrict__ out) {
    int idx = blockIdx.x * blockDim.x + threadIdx.x;
    if (idx >= NB*DD*TT) return;
    int t = idx & (TT-1);
    int d = (idx >> 8) & (DD-1);
    int b = idx >> 15;
    out[idx] = g_x2[(size_t)(b*TT + t)*DD + d];
}

// ---------------- pred head ----------------
__global__ void k_pred(const float* __restrict__ xflat, const float* __restrict__ fcw,
                       const float* __restrict__ fcb, float* __restrict__ pred) {
    __shared__ float red[8];
    int c = blockIdx.x, b = blockIdx.y, tid = threadIdx.x;
    const float4* x4 = (const float4*)(xflat + (size_t)b * (DD*TT));
    const float4* w4 = (const float4*)(fcw + (size_t)c * (DD*TT));
    float s = 0.0f;
    for (int i = tid; i < DD*TT/4; i += blockDim.x) {
        float4 a = x4[i], w = w4[i];
        s += a.x*w.x + a.y*w.y + a.z*w.z + a.w*w.w;
    }
    #pragma unroll
    for (int o = 16; o > 0; o >>= 1) s += __shfl_xor_sync(0xffffffffu, s, o);
    if ((tid & 31) == 0) red[tid >> 5] = s;
    __syncthreads();
    if (tid == 0) {
        float tot = 0.0f;
        for (int i = 0; i < (int)(blockDim.x >> 5); i++) tot += red[i];
        pred[b*CC + c] = tot + fcb[c];
    }
}

// ---------------- launch ----------------
extern "C" void kernel_launch(void* const* d_in, const int* in_sizes, int n_in,
                              void* d_out, int out_size) {
    const float* inputs    = (const float*)d_in[0];
    const float* emb_w     = (const float*)d_in[1];
    const float* emb_b     = (const float*)d_in[2];
    const float* blk_dw_w  = (const float*)d_in[3];
    const float* blk_dw_b  = (const float*)d_in[4];
    const float* blk_pw_w  = (const float*)d_in[5];
    const float* blk_pw_b  = (const float*)d_in[6];
    const float* blk_se_w1 = (const float*)d_in[7];
    const float* blk_se_b1 = (const float*)d_in[8];
    const float* blk_se_w2 = (const float*)d_in[9];
    const float* blk_se_b2 = (const float*)d_in[10];
    const float* mam_in_w  = (const float*)d_in[11];
    const float* mam_conv_w= (const float*)d_in[12];
    const float* mam_conv_b= (const float*)d_in[13];
    const float* mam_xproj = (const float*)d_in[14];
    const float* mam_dt_w  = (const float*)d_in[15];
    const float* mam_dt_b  = (const float*)d_in[16];
    const float* mam_Alog  = (const float*)d_in[17];
    const float* mam_D     = (const float*)d_in[18];
    const float* mam_out_w = (const float*)d_in[19];
    const float* ln_g      = (const float*)d_in[20];
    const float* ln_b      = (const float*)d_in[21];
    const float* fc_w      = (const float*)d_in[22];
    const float* fc_b      = (const float*)d_in[23];
    float* out = (float*)d_out;

    k_emb<<<BMR, 256>>>(inputs, emb_w, emb_b);

    for (int i = 0; i < NLB; i++) {
        k_dwgelu<<<(BMR*DD*TT)/256, 256>>>(blk_dw_w + i*DD*KC, blk_dw_b + i*DD);
        k_pw_gemm<<<dim3(2,1,BMR), 256>>>(blk_pw_w + i*DD*DD, blk_pw_b + i*DD);
        k_mean<<<BMR, DD>>>();
        k_se<<<BMR, DD>>>(blk_se_w1 + i*DR*DD, blk_se_b1 + i*DR,
                          blk_se_w2 + i*DD*DR, blk_se_b2 + i*DD);
        k_apply<<<(BMR*DD*TT)/256, 256>>>();
    }

    k_smean<<<dim3(TT, NB), DD>>>();

    for (int i = 0; i < NMB; i++) {
        k_gemm_nt<<<dim3(4, BT/128), 256>>>(0, mam_in_w + (size_t)i*2*DI*DD, DD);
        k_convsilu<<<(BT*DI)/256, 256>>>(mam_conv_w + i*DI*DCV, mam_conv_b + i*DI);
        k_dbl<<<BT/32, 256>>>(mam_xproj + i*40*DI);
        k_dt<<<(BT*DI)/256, 256>>>(mam_dt_w + i*DI*RKD, mam_dt_b + i*DI);
        k_scan<<<dim3(DI/128, NB), 128>>>(mam_Alog + i*DI*DSN, mam_D + i*DI);
        k_gemm_nt<<<dim3(1, BT/128), 256>>>(1, mam_out_w + (size_t)i*DD*DI, DI);
        k_ln<<<BT, DD>>>(ln_g + i*DD, ln_b + i*DD);
    }

    k_xflat<<<(NB*DD*TT)/256, 256>>>(out);
    k_pred<<<dim3(CC, NB), 256>>>(out, fc_w, fc_b, out + (size_t)NB*DD*TT);
}